// round 3
// baseline (speedup 1.0000x reference)
#include <cuda_runtime.h>
#include <math.h>

#define Bn   32
#define Nn   1024
#define FIN  512
#define H1n  256
#define H2n  128

// ---- scratch (device globals; no allocation allowed) ----
__device__ float g_h1[Bn * Nn * H1n];   // 32 MB
__device__ float g_g1[Bn * Nn * H1n];   // 32 MB
__device__ float g_h2[Bn * Nn * H2n];   // 16 MB
__device__ float g_el[Bn * Nn];
__device__ float g_er[Bn * Nn];
__device__ float g_sb[Bn * 2];          // per-batch (scale, bias)
__device__ float g_v[Bn * Nn];          // g2 @ Wg

// ============================================================
// Generic fp32 GEMM: C[M,N] = A[M,K] * B[K,N]
// BM=128, BN=64, BK=8, 256 threads, 8x4 per thread
// ============================================================
__global__ __launch_bounds__(256) void gemm_kernel(
    const float* __restrict__ A, const float* __restrict__ B,
    float* __restrict__ C, int M, int N, int K)
{
    __shared__ float As[8][132];   // padded, transposed
    __shared__ float Bs[8][64];
    int t = threadIdx.x;
    int bm = blockIdx.y * 128, bn = blockIdx.x * 64;
    int tcol = (t & 15) * 4;
    int trow = (t >> 4) * 8;
    float acc[8][4];
#pragma unroll
    for (int i = 0; i < 8; i++)
#pragma unroll
        for (int j = 0; j < 4; j++) acc[i][j] = 0.f;

    int arow = t >> 1, ak = (t & 1) * 4;
    for (int k0 = 0; k0 < K; k0 += 8) {
        float4 av = *(const float4*)&A[(size_t)(bm + arow) * K + k0 + ak];
        As[ak + 0][arow] = av.x; As[ak + 1][arow] = av.y;
        As[ak + 2][arow] = av.z; As[ak + 3][arow] = av.w;
        if (t < 128) {
            int bk = t >> 4, bc = (t & 15) * 4;
            *(float4*)&Bs[bk][bc] = *(const float4*)&B[(size_t)(k0 + bk) * N + bn + bc];
        }
        __syncthreads();
#pragma unroll
        for (int kk = 0; kk < 8; kk++) {
            float4 b4 = *(const float4*)&Bs[kk][tcol];
            float4 a0 = *(const float4*)&As[kk][trow];
            float4 a1 = *(const float4*)&As[kk][trow + 4];
            float ar[8] = {a0.x, a0.y, a0.z, a0.w, a1.x, a1.y, a1.z, a1.w};
#pragma unroll
            for (int ii = 0; ii < 8; ii++) {
                acc[ii][0] += ar[ii] * b4.x;
                acc[ii][1] += ar[ii] * b4.y;
                acc[ii][2] += ar[ii] * b4.z;
                acc[ii][3] += ar[ii] * b4.w;
            }
        }
        __syncthreads();
    }
#pragma unroll
    for (int ii = 0; ii < 8; ii++) {
        *(float4*)&C[(size_t)(bm + trow + ii) * N + bn + tcol] =
            make_float4(acc[ii][0], acc[ii][1], acc[ii][2], acc[ii][3]);
    }
}

// ============================================================
// el/er: per row dot with a[0:Fo] and a[Fo:2Fo]. One warp/row.
// ============================================================
__global__ __launch_bounds__(256) void eler_kernel(
    const float* __restrict__ h, const float* __restrict__ a,
    float* __restrict__ el, float* __restrict__ er, int Fo)
{
    int row = (blockIdx.x * blockDim.x + threadIdx.x) >> 5;
    int lane = threadIdx.x & 31;
    if (row >= Bn * Nn) return;
    const float* hr = h + (size_t)row * Fo;
    float sl = 0.f, sr = 0.f;
    for (int f = lane; f < Fo; f += 32) {
        float hv = hr[f];
        sl += hv * a[f];
        sr += hv * a[Fo + f];
    }
#pragma unroll
    for (int o = 16; o; o >>= 1) {
        sl += __shfl_xor_sync(0xffffffffu, sl, o);
        sr += __shfl_xor_sync(0xffffffffu, sr, o);
    }
    if (lane == 0) { el[row] = sl; er[row] = sr; }
}

// ============================================================
// per-batch min/max of el, er -> scale/bias for sigmoid arg
// e = (leaky(el_i+er_j) - mn)/(mx-mn)*30 - 20
// mn = leaky(min el + min er), mx = leaky(max el + max er)
// ============================================================
__global__ __launch_bounds__(256) void minmax_kernel(
    const float* __restrict__ el, const float* __restrict__ er,
    float* __restrict__ sb)
{
    int b = blockIdx.x, t = threadIdx.x;
    const float* e1 = el + b * Nn;
    const float* e2 = er + b * Nn;
    float mnl = 1e30f, mxl = -1e30f, mnr = 1e30f, mxr = -1e30f;
    for (int i = t; i < Nn; i += 256) {
        float a = e1[i]; mnl = fminf(mnl, a); mxl = fmaxf(mxl, a);
        float c = e2[i]; mnr = fminf(mnr, c); mxr = fmaxf(mxr, c);
    }
#pragma unroll
    for (int o = 16; o; o >>= 1) {
        mnl = fminf(mnl, __shfl_xor_sync(0xffffffffu, mnl, o));
        mxl = fmaxf(mxl, __shfl_xor_sync(0xffffffffu, mxl, o));
        mnr = fminf(mnr, __shfl_xor_sync(0xffffffffu, mnr, o));
        mxr = fmaxf(mxr, __shfl_xor_sync(0xffffffffu, mxr, o));
    }
    __shared__ float s[8][4];
    int w = t >> 5, lane = t & 31;
    if (lane == 0) { s[w][0] = mnl; s[w][1] = mxl; s[w][2] = mnr; s[w][3] = mxr; }
    __syncthreads();
    if (t == 0) {
#pragma unroll
        for (int i = 1; i < 8; i++) {
            mnl = fminf(mnl, s[i][0]); mxl = fmaxf(mxl, s[i][1]);
            mnr = fminf(mnr, s[i][2]); mxr = fmaxf(mxr, s[i][3]);
        }
        float emin = mnl + mnr; emin = emin >= 0.f ? emin : 0.01f * emin;
        float emax = mxl + mxr; emax = emax >= 0.f ? emax : 0.01f * emax;
        float sc = 30.f / (emax - emin);
        sb[b * 2] = sc;
        sb[b * 2 + 1] = -emin * sc - 20.f;
    }
}

// ============================================================
// Fused layer-1 attention GEMM:
// g1[b,i,f] = elu( sum_j sigmoid(scale*leaky(el_i+er_j)+bias) * h1[b,j,f] )
// Block: 32 i-rows x 256 f (full width). 256 threads, 8x4 each.
// ============================================================
__global__ __launch_bounds__(256) void fused_att1_kernel(
    const float* __restrict__ h, const float* __restrict__ el,
    const float* __restrict__ er, const float* __restrict__ sb,
    float* __restrict__ out)
{
    __shared__ float hs[32][256];   // 32 KB
    __shared__ float atts[32][33];
    int b = blockIdx.y;
    int i0 = blockIdx.x * 32;
    int t = threadIdx.x;
    float scale = sb[b * 2], bias = sb[b * 2 + 1];
    int fcol = (t & 63) * 4;
    int ir0 = (t >> 6) * 8;
    float acc[8][4];
#pragma unroll
    for (int i = 0; i < 8; i++)
#pragma unroll
        for (int j = 0; j < 4; j++) acc[i][j] = 0.f;

    const float* hb = h + (size_t)b * Nn * H1n;
    const float* elb = el + b * Nn;
    const float* erb = er + b * Nn;

    for (int j0 = 0; j0 < Nn; j0 += 32) {
#pragma unroll
        for (int r = 0; r < 8; r++) {
            int idx = t + r * 256;
            int jj = idx >> 6, f4 = (idx & 63) * 4;
            *(float4*)&hs[jj][f4] = *(const float4*)&hb[(size_t)(j0 + jj) * H1n + f4];
        }
#pragma unroll
        for (int r = 0; r < 4; r++) {
            int idx = t * 4 + r;
            int i = idx >> 5, j = idx & 31;
            float x = elb[i0 + i] + erb[j0 + j];
            x = x >= 0.f ? x : 0.01f * x;
            x = scale * x + bias;
            atts[i][j] = 1.f / (1.f + __expf(-x));
        }
        __syncthreads();
#pragma unroll
        for (int jj = 0; jj < 32; jj++) {
            float4 hv = *(const float4*)&hs[jj][fcol];
#pragma unroll
            for (int ii = 0; ii < 8; ii++) {
                float a = atts[ir0 + ii][jj];
                acc[ii][0] += a * hv.x;
                acc[ii][1] += a * hv.y;
                acc[ii][2] += a * hv.z;
                acc[ii][3] += a * hv.w;
            }
        }
        __syncthreads();
    }
    float* ob = out + (size_t)b * Nn * H1n;
#pragma unroll
    for (int ii = 0; ii < 8; ii++) {
        float4 v;
        v.x = acc[ii][0] > 0.f ? acc[ii][0] : __expf(acc[ii][0]) - 1.f;
        v.y = acc[ii][1] > 0.f ? acc[ii][1] : __expf(acc[ii][1]) - 1.f;
        v.z = acc[ii][2] > 0.f ? acc[ii][2] : __expf(acc[ii][2]) - 1.f;
        v.w = acc[ii][3] > 0.f ? acc[ii][3] : __expf(acc[ii][3]) - 1.f;
        *(float4*)&ob[(size_t)(i0 + ir0 + ii) * H1n + fcol] = v;
    }
}

// ============================================================
// Fused layer-2 attention GEMM. Also writes fc2 (= att2) output.
// Block: 64 i-rows x 128 f. 256 threads, 8x4 each.
// ============================================================
__global__ __launch_bounds__(256) void fused_att2_kernel(
    const float* __restrict__ h, const float* __restrict__ el,
    const float* __restrict__ er, const float* __restrict__ sb,
    float* __restrict__ fc2, float* __restrict__ g2)
{
    __shared__ float hs[32][128];   // 16 KB
    __shared__ float atts[64][33];  // 8.4 KB
    int b = blockIdx.y;
    int i0 = blockIdx.x * 64;
    int t = threadIdx.x;
    float scale = sb[b * 2], bias = sb[b * 2 + 1];
    int fcol = (t & 31) * 4;
    int ir0 = (t >> 5) * 8;
    float acc[8][4];
#pragma unroll
    for (int i = 0; i < 8; i++)
#pragma unroll
        for (int j = 0; j < 4; j++) acc[i][j] = 0.f;

    const float* hb = h + (size_t)b * Nn * H2n;
    const float* elb = el + b * Nn;
    const float* erb = er + b * Nn;
    int arow = t >> 2;            // i within tile for att store
    int jbase = (t & 3) * 8;      // j base for att store

    for (int j0 = 0; j0 < Nn; j0 += 32) {
#pragma unroll
        for (int r = 0; r < 4; r++) {
            int idx = t + r * 256;
            int jj = idx >> 5, f4 = (idx & 31) * 4;
            *(float4*)&hs[jj][f4] = *(const float4*)&hb[(size_t)(j0 + jj) * H2n + f4];
        }
        float av[8];
        float eli = elb[i0 + arow];
#pragma unroll
        for (int r = 0; r < 8; r++) {
            float x = eli + erb[j0 + jbase + r];
            x = x >= 0.f ? x : 0.01f * x;
            x = scale * x + bias;
            float s = 1.f / (1.f + __expf(-x));
            av[r] = s;
            atts[arow][jbase + r] = s;
        }
        // write att tile to fc2 output (coalesced, 2x float4 per thread)
        float* fr = fc2 + (size_t)(b * Nn + i0 + arow) * Nn + j0 + jbase;
        *(float4*)&fr[0] = make_float4(av[0], av[1], av[2], av[3]);
        *(float4*)&fr[4] = make_float4(av[4], av[5], av[6], av[7]);
        __syncthreads();
#pragma unroll
        for (int jj = 0; jj < 32; jj++) {
            float4 hv = *(const float4*)&hs[jj][fcol];
#pragma unroll
            for (int ii = 0; ii < 8; ii++) {
                float a = atts[ir0 + ii][jj];
                acc[ii][0] += a * hv.x;
                acc[ii][1] += a * hv.y;
                acc[ii][2] += a * hv.z;
                acc[ii][3] += a * hv.w;
            }
        }
        __syncthreads();
    }
    float* ob = g2 + (size_t)b * Nn * H2n;
#pragma unroll
    for (int ii = 0; ii < 8; ii++) {
        *(float4*)&ob[(size_t)(i0 + ir0 + ii) * H2n + fcol] =
            make_float4(acc[ii][0], acc[ii][1], acc[ii][2], acc[ii][3]);
    }
}

// ============================================================
// v[b,j] = g2[b,j,:] . Wg  (one warp per row)
// ============================================================
__global__ __launch_bounds__(256) void v_kernel(
    const float* __restrict__ g2, const float* __restrict__ Wg,
    float* __restrict__ v)
{
    int row = (blockIdx.x * blockDim.x + threadIdx.x) >> 5;
    int lane = threadIdx.x & 31;
    if (row >= Bn * Nn) return;
    const float* g = g2 + (size_t)row * H2n;
    float s = 0.f;
#pragma unroll
    for (int f = lane; f < H2n; f += 32) s += g[f] * Wg[f];
#pragma unroll
    for (int o = 16; o; o >>= 1) s += __shfl_xor_sync(0xffffffffu, s, o);
    if (lane == 0) v[row] = s;
}

// ============================================================
// out[b,i] = leaky( sum_j fc2[b,i,j]*v[b,j] + bg, 0.01 )
// One block (256 threads) per row.
// ============================================================
__global__ __launch_bounds__(256) void z_kernel(
    const float* __restrict__ fc2, const float* __restrict__ v,
    const float* __restrict__ bg, float* __restrict__ out)
{
    int row = blockIdx.x;
    int b = row >> 10;
    int t = threadIdx.x;
    const float* fr = fc2 + (size_t)row * Nn;
    const float* vb = v + b * Nn;
    float4 f4 = *(const float4*)&fr[t * 4];
    float4 v4 = *(const float4*)&vb[t * 4];
    float s = f4.x * v4.x + f4.y * v4.y + f4.z * v4.z + f4.w * v4.w;
    __shared__ float red[256];
    red[t] = s;
    __syncthreads();
#pragma unroll
    for (int o = 128; o > 0; o >>= 1) {
        if (t < o) red[t] += red[t + o];
        __syncthreads();
    }
    if (t == 0) {
        float z = red[0] + bg[0];
        out[row] = z >= 0.f ? z : 0.01f * z;
    }
}

// ============================================================
extern "C" void kernel_launch(void* const* d_in, const int* in_sizes, int n_in,
                              void* d_out, int out_size)
{
    const float* x  = (const float*)d_in[0];
    // d_in[1] = edge_weight (unused by reference)
    const float* W1 = (const float*)d_in[2];
    const float* a1 = (const float*)d_in[3];
    const float* W2 = (const float*)d_in[4];
    const float* a2 = (const float*)d_in[5];
    const float* Wg = (const float*)d_in[6];
    const float* bg = (const float*)d_in[7];

    float* out = (float*)d_out;
    float* fc2 = out + (size_t)Bn * Nn;
    float* g2  = fc2 + (size_t)Bn * Nn * Nn;

    float *h1, *g1, *h2, *el, *er, *sb, *vv;
    cudaGetSymbolAddress((void**)&h1, g_h1);
    cudaGetSymbolAddress((void**)&g1, g_g1);
    cudaGetSymbolAddress((void**)&h2, g_h2);
    cudaGetSymbolAddress((void**)&el, g_el);
    cudaGetSymbolAddress((void**)&er, g_er);
    cudaGetSymbolAddress((void**)&sb, g_sb);
    cudaGetSymbolAddress((void**)&vv, g_v);

    const int M = Bn * Nn;   // 32768

    // 1) h1 = x @ W1   [32768,512]x[512,256]
    gemm_kernel<<<dim3(H1n / 64, M / 128), 256>>>(x, W1, h1, M, H1n, FIN);
    // 2) el1/er1
    eler_kernel<<<M / 8, 256>>>(h1, a1, el, er, H1n);
    // 3) per-batch scale/bias
    minmax_kernel<<<Bn, 256>>>(el, er, sb);
    // 4) g1 = elu(att1 @ h1)
    fused_att1_kernel<<<dim3(Nn / 32, Bn), 256>>>(h1, el, er, sb, g1);
    // 5) h2 = g1 @ W2   [32768,256]x[256,128]
    gemm_kernel<<<dim3(H2n / 64, M / 128), 256>>>(g1, W2, h2, M, H2n, H1n);
    // 6) el2/er2
    eler_kernel<<<M / 8, 256>>>(h2, a2, el, er, H2n);
    // 7) scale/bias
    minmax_kernel<<<Bn, 256>>>(el, er, sb);
    // 8) fc2 (written) + g2 = att2 @ h2
    fused_att2_kernel<<<dim3(Nn / 64, Bn), 256>>>(h2, el, er, sb, fc2, g2);
    // 9) v = g2 @ Wg
    v_kernel<<<M / 8, 256>>>(g2, Wg, vv);
    // 10) out = leaky(fc2 @ v + bg)
    z_kernel<<<M, 256>>>(fc2, vv, bg, out);
}